// round 1
// baseline (speedup 1.0000x reference)
#include <cuda_runtime.h>

#define LATENT   16
#define NREP     10
#define NSTEPS   10
#define NLIB     169
#define DT_F     0.01f

// ---- packed f32x2 helpers (sm_100a family) ----
__device__ __forceinline__ unsigned long long pack2(float lo, float hi) {
    unsigned long long r;
    asm("mov.b64 %0, {%1, %2};" : "=l"(r) : "f"(lo), "f"(hi));
    return r;
}
__device__ __forceinline__ unsigned long long fma2(unsigned long long a,
                                                   unsigned long long b,
                                                   unsigned long long c) {
    unsigned long long d;
    asm("fma.rn.f32x2 %0, %1, %2, %3;" : "=l"(d) : "l"(a), "l"(b), "l"(c));
    return d;
}
__device__ __forceinline__ void unpack2(unsigned long long v, float& lo, float& hi) {
    asm("mov.b64 {%0, %1}, %2;" : "=f"(lo), "=f"(hi) : "l"(v));
}

__global__ __launch_bounds__(256)
void sindy_shred_kernel(const float* __restrict__ h_t,
                        const float* __restrict__ coeff,
                        const float* __restrict__ mask,
                        float* __restrict__ out,
                        int n_total)
{
    // Masked coefficients for this block's replicate, packed as f32x2 pairs.
    // Layout: C2[l*8 + k] = (C[l][2k], C[l][2k+1]); 169*8*8B = 10816 B.
    __shared__ unsigned long long C2[NLIB * 8];

    const int r = blockIdx.y;
    {
        const float* cr = coeff + (size_t)r * NLIB * LATENT;
        const float* mr = mask  + (size_t)r * NLIB * LATENT;
        for (int idx = threadIdx.x; idx < NLIB * 8; idx += blockDim.x) {
            int base = idx * 2;
            float a = cr[base]     * mr[base];
            float b = cr[base + 1] * mr[base + 1];
            C2[idx] = pack2(a, b);
        }
    }
    __syncthreads();

    const int n = blockIdx.x * blockDim.x + threadIdx.x;
    if (n >= n_total) return;

    // Load h_t[n][0:16] into registers.
    float z[LATENT];
    {
        const float4* hin = reinterpret_cast<const float4*>(h_t + (size_t)n * LATENT);
        #pragma unroll
        for (int k = 0; k < 4; k++) {
            float4 v = hin[k];
            z[4*k + 0] = v.x; z[4*k + 1] = v.y;
            z[4*k + 2] = v.z; z[4*k + 3] = v.w;
        }
    }

    for (int step = 0; step < NSTEPS; step++) {
        // acc[k] holds packed (dz[2k], dz[2k+1]); init with constant term row 0.
        unsigned long long acc[8];
        #pragma unroll
        for (int k = 0; k < 8; k++) acc[k] = C2[k];

        int l = 1;

        // Linear terms: theta_l = z[i]
        #pragma unroll 4
        for (int i = 0; i < LATENT; i++) {
            unsigned long long t2 = pack2(z[i], z[i]);
            const unsigned long long* row = &C2[l * 8];
            #pragma unroll
            for (int k = 0; k < 8; k++) acc[k] = fma2(t2, row[k], acc[k]);
            l++;
        }

        // Quadratic terms: theta = z[i]*z[j], i<=j, triu row-major order
        for (int i = 0; i < LATENT; i++) {
            float zi = z[i];
            for (int j = i; j < LATENT; j++) {
                float t = zi * z[j];
                unsigned long long t2 = pack2(t, t);
                const unsigned long long* row = &C2[l * 8];
                #pragma unroll
                for (int k = 0; k < 8; k++) acc[k] = fma2(t2, row[k], acc[k]);
                l++;
            }
        }

        // Sine terms: theta = sin(z[i])
        #pragma unroll 4
        for (int i = 0; i < LATENT; i++) {
            float s = __sinf(z[i]);
            unsigned long long t2 = pack2(s, s);
            const unsigned long long* row = &C2[l * 8];
            #pragma unroll
            for (int k = 0; k < 8; k++) acc[k] = fma2(t2, row[k], acc[k]);
            l++;
        }

        // Euler step: z[d] += dz[d] * DT  (FFMA with immediate multiplier)
        #pragma unroll
        for (int k = 0; k < 8; k++) {
            float lo, hi;
            unpack2(acc[k], lo, hi);
            z[2*k + 0] = fmaf(lo, DT_F, z[2*k + 0]);
            z[2*k + 1] = fmaf(hi, DT_F, z[2*k + 1]);
        }
    }

    // Store out[n][r][0:16]
    {
        float4* po = reinterpret_cast<float4*>(out + ((size_t)n * NREP + r) * LATENT);
        #pragma unroll
        for (int k = 0; k < 4; k++) {
            po[k] = make_float4(z[4*k + 0], z[4*k + 1], z[4*k + 2], z[4*k + 3]);
        }
    }
}

extern "C" void kernel_launch(void* const* d_in, const int* in_sizes, int n_in,
                              void* d_out, int out_size)
{
    const float* h_t   = (const float*)d_in[0];   // [50000, 16]
    const float* coeff = (const float*)d_in[1];   // [10, 169, 16]
    const float* mask  = (const float*)d_in[2];   // [10, 169, 16]
    float* out = (float*)d_out;                   // [50000, 10, 16]

    int n_total = in_sizes[0] / LATENT;
    dim3 grid((unsigned)((n_total + 255) / 256), NREP, 1);
    sindy_shred_kernel<<<grid, 256>>>(h_t, coeff, mask, out, n_total);
}